// round 5
// baseline (speedup 1.0000x reference)
#include <cuda_runtime.h>
#include <cuda_bf16.h>
#include <math_constants.h>

// Problem constants
#define B_    128
#define T_    1024
#define D_    512
#define V_    128
#define L_    128
#define S_    257           // 2L+1
#define BLANK_ 127          // V-1
#define EPS_  1e-7f
#define NEG_  (-1e30f)

// Scratch: probabilities [B,T,V] fp32 (64 MB), per-example losses
static __device__ float g_probs[B_ * T_ * V_];
static __device__ float g_loss[B_];

// ---------------------------------------------------------------------------
// Kernel 1: fused GEMM (logits = X @ W + b) + row softmax -> g_probs
// M = B*T = 131072 rows, N = V = 128, K = D = 512.
// Block tile 128x128, BK=8, 256 threads, 8x8 micro-tile per thread.
// Each 16-thread half-warp (same ty) owns 8 full rows -> shfl softmax.
// ---------------------------------------------------------------------------
__global__ __launch_bounds__(256) void gemm_softmax_kernel(
    const float* __restrict__ X, const float* __restrict__ W,
    const float* __restrict__ bias)
{
    __shared__ float As[8][128];   // [k][m]
    __shared__ float Bs[8][128];   // [k][n]

    const int tid = threadIdx.x;
    const int tx = tid & 15;        // col group 0..15
    const int ty = tid >> 4;        // row group 0..15
    const int rowBase = blockIdx.x * 128;

    float acc[8][8];
#pragma unroll
    for (int i = 0; i < 8; ++i)
#pragma unroll
        for (int j = 0; j < 8; ++j) acc[i][j] = 0.f;

    const int lr = tid >> 1;             // 0..127 A row
    const int lk = (tid & 1) * 4;        // 0 or 4  A k-offset
    const int bk = tid >> 5;             // 0..7    B k-row
    const int bc = (tid & 31) * 4;       // B col (float4)
    const float* Xp = X + (size_t)(rowBase + lr) * D_ + lk;
    const float* Wp = W + bk * V_ + bc;

    for (int k0 = 0; k0 < D_; k0 += 8) {
        float4 av = *(const float4*)(Xp + k0);
        float4 bv = *(const float4*)(Wp + k0 * V_);
        As[lk + 0][lr] = av.x; As[lk + 1][lr] = av.y;
        As[lk + 2][lr] = av.z; As[lk + 3][lr] = av.w;
        *(float4*)&Bs[bk][bc] = bv;
        __syncthreads();
#pragma unroll
        for (int kk = 0; kk < 8; ++kk) {
            float4 a0 = *(const float4*)&As[kk][ty * 8];
            float4 a1 = *(const float4*)&As[kk][ty * 8 + 4];
            float4 b0 = *(const float4*)&Bs[kk][tx * 8];
            float4 b1 = *(const float4*)&Bs[kk][tx * 8 + 4];
            float a[8]   = {a0.x, a0.y, a0.z, a0.w, a1.x, a1.y, a1.z, a1.w};
            float bb2[8] = {b0.x, b0.y, b0.z, b0.w, b1.x, b1.y, b1.z, b1.w};
#pragma unroll
            for (int i = 0; i < 8; ++i)
#pragma unroll
                for (int j = 0; j < 8; ++j)
                    acc[i][j] = fmaf(a[i], bb2[j], acc[i][j]);
        }
        __syncthreads();
    }

    // Epilogue: + bias, softmax per row, store probabilities.
    float bb[8];
#pragma unroll
    for (int j = 0; j < 8; ++j) bb[j] = bias[tx * 8 + j];

#pragma unroll
    for (int i = 0; i < 8; ++i) {
        float l[8];
        float rmax = -CUDART_INF_F;
#pragma unroll
        for (int j = 0; j < 8; ++j) { l[j] = acc[i][j] + bb[j]; rmax = fmaxf(rmax, l[j]); }
#pragma unroll
        for (int m = 1; m <= 8; m <<= 1)
            rmax = fmaxf(rmax, __shfl_xor_sync(0xFFFFFFFFu, rmax, m));
        float s = 0.f;
#pragma unroll
        for (int j = 0; j < 8; ++j) { l[j] = __expf(l[j] - rmax); s += l[j]; }
#pragma unroll
        for (int m = 1; m <= 8; m <<= 1)
            s += __shfl_xor_sync(0xFFFFFFFFu, s, m);
        float invs = 1.f / s;
        float* orow = g_probs + (size_t)(rowBase + ty * 8 + i) * V_ + tx * 8;
        float4 o0 = {l[0] * invs, l[1] * invs, l[2] * invs, l[3] * invs};
        float4 o1 = {l[4] * invs, l[5] * invs, l[6] * invs, l[7] * invs};
        *(float4*)orow = o0;
        *(float4*)(orow + 4) = o1;
    }
}

// ---------------------------------------------------------------------------
// Kernel 2: CTC forward DP in LOG space (matches reference semantics).
// One block per example; 288 threads (9 warps), thread s owns state s (<257).
// Per step: threads <128 compute lp[v] = log(p[v]+eps) (prob row prefetched
// into a register one step ahead); each state does a 3-way logaddexp.
// -1e30 sentinels are absorbing in fp32, mirroring the reference's NEG.
// ---------------------------------------------------------------------------
__global__ __launch_bounds__(288) void ctc_kernel(
    const int* __restrict__ targets, const int* __restrict__ tlen)
{
    __shared__ float alpha[2][S_];
    __shared__ float lp[2][V_];
    __shared__ int   exts[S_];

    const int b = blockIdx.x;
    const int tid = threadIdx.x;
    const float* P = g_probs + (size_t)b * T_ * V_;

    // Extended label sequence: blank, l1, blank, l2, ..., blank
    if (tid < S_) exts[tid] = (tid & 1) ? targets[b * L_ + (tid >> 1)] : BLANK_;

    // Stage log-row t=0, prefetch prob row t=1
    float pf = 0.f;
    if (tid < V_) { lp[0][tid] = __logf(P[tid] + EPS_); pf = P[V_ + tid]; }
    __syncthreads();

    int  myext  = 0;
    bool allow2 = false;
    if (tid < S_) {
        myext  = exts[tid];
        allow2 = (tid & 1) && (tid >= 2) && (myext != exts[tid - 2]);
        alpha[0][tid] = (tid < 2) ? lp[0][myext] : NEG_;
    }

    for (int t = 1; t < T_; ++t) {
        const int cur = t & 1, prev = cur ^ 1;
        if (tid < V_) {
            lp[cur][tid] = __logf(pf + EPS_);
            if (t + 1 < T_) pf = P[(size_t)(t + 1) * V_ + tid];
        }
        __syncthreads();   // alpha[prev] (from last iter) + lp[cur] ready

        if (tid < S_) {
            float a  = alpha[prev][tid];
            float a1 = (tid >= 1) ? alpha[prev][tid - 1] : NEG_;
            float a2 = allow2 ? alpha[prev][tid - 2] : NEG_;
            float m  = fmaxf(fmaxf(a, a1), a2);
            float s  = __expf(a - m) + __expf(a1 - m) + __expf(a2 - m);
            alpha[cur][tid] = m + __logf(s) + lp[cur][myext];
        }
        // single barrier per step: next iteration's top-of-loop sync orders
        // these alpha writes before their reads (lp is double-buffered).
    }
    __syncthreads();

    if (tid == 0) {
        const int last = 2 * tlen[b];              // 2..256
        // (T_-1)&1 == 1 -> final alpha lives in buffer 1.
        float aN  = alpha[1][last];
        float aN1 = alpha[1][last - 1];
        float m   = fmaxf(aN, aN1);
        g_loss[b] = -(m + __logf(__expf(aN - m) + __expf(aN1 - m)));
    }
}

// ---------------------------------------------------------------------------
// Kernel 3: deterministic fixed-order sum of the 128 losses.
// ---------------------------------------------------------------------------
__global__ __launch_bounds__(128) void sum_kernel(float* __restrict__ out)
{
    __shared__ float s[128];
    const int t = threadIdx.x;
    s[t] = g_loss[t];
    __syncthreads();
    for (int o = 64; o > 0; o >>= 1) {
        if (t < o) s[t] += s[t + o];
        __syncthreads();
    }
    if (t == 0) out[0] = s[0];
}

extern "C" void kernel_launch(void* const* d_in, const int* in_sizes, int n_in,
                              void* d_out, int out_size)
{
    (void)in_sizes; (void)n_in; (void)out_size;
    const float* x       = (const float*)d_in[0];
    const float* W       = (const float*)d_in[1];
    const float* bias    = (const float*)d_in[2];
    const int*   targets = (const int*)d_in[3];
    const int*   tlength = (const int*)d_in[4];

    gemm_softmax_kernel<<<(B_ * T_) / 128, 256>>>(x, W, bias);
    ctc_kernel<<<B_, 288>>>(targets, tlength);
    sum_kernel<<<1, 128>>>((float*)d_out);
}

// round 6
// speedup vs baseline: 1.3542x; 1.3542x over previous
#include <cuda_runtime.h>
#include <cuda_bf16.h>
#include <math_constants.h>
#include <mma.h>

using namespace nvcuda;

// Problem constants
#define B_    128
#define T_    1024
#define D_    512
#define V_    128
#define L_    128
#define S_    257           // 2L+1
#define BLANK_ 127          // V-1
#define EPS_  1e-7f
#define NEG_  (-1e30f)
#define LN2_  0.6931471805599453f

// GEMM tiling
#define BM 128
#define BN 128
#define BK 32
#define APAD 8
#define BPAD 8
#define CPAD 4

// Scratch: log2(softmax prob + eps) [B,T,V] fp32 (64 MB), per-example losses
static __device__ float g_lp[B_ * T_ * V_];
static __device__ float g_loss[B_];

__device__ __forceinline__ float fexp2(float x) {
    float y; asm("ex2.approx.ftz.f32 %0, %1;" : "=f"(y) : "f"(x)); return y;
}

__device__ __forceinline__ void st4bf16(__nv_bfloat16* dst, float4 v) {
    __nv_bfloat162 p0; p0.x = __float2bfloat16(v.x); p0.y = __float2bfloat16(v.y);
    __nv_bfloat162 p1; p1.x = __float2bfloat16(v.z); p1.y = __float2bfloat16(v.w);
    *(__nv_bfloat162*)(dst)     = p0;
    *(__nv_bfloat162*)(dst + 2) = p1;
}

// ---------------------------------------------------------------------------
// Kernel 1: bf16 WMMA GEMM (logits = X @ W + b) + softmax -> g_lp = log2(p+eps)
// M = B*T = 131072, N = V = 128, K = D = 512. fp32 accumulate.
// Block 128x128, BK=32, 8 warps: warp grid 4(M) x 2(N), warp tile 32x64.
// Epilogue: 4 passes of 32 rows through smem; softmax via half-warp shuffles.
// ---------------------------------------------------------------------------
__global__ __launch_bounds__(256) void gemm_softmax_kernel(
    const float* __restrict__ X, const float* __restrict__ W,
    const float* __restrict__ bias)
{
    __shared__ __nv_bfloat16 As[BM][BK + APAD];   // 128 x 40  (10.2 KB)
    __shared__ __nv_bfloat16 Bs[BK][BN + BPAD];   //  32 x 136 ( 8.7 KB)
    __shared__ float         Cs[32][BN + CPAD];   //  32 x 132 (16.9 KB)

    const int tid = threadIdx.x;
    const int wid = tid >> 5;
    const int warp_m = wid & 3;       // 0..3
    const int warp_n = wid >> 2;      // 0..1
    const int rowBase = blockIdx.x * BM;

    wmma::fragment<wmma::accumulator, 16, 16, 16, float> cfrag[2][4];
#pragma unroll
    for (int i = 0; i < 2; ++i)
#pragma unroll
        for (int j = 0; j < 4; ++j) wmma::fill_fragment(cfrag[i][j], 0.f);

    // Load mapping: A slab 128x32 fp32 (each thread: 16 consecutive floats)
    const int ar = tid >> 1;
    const int ac = (tid & 1) * 16;
    const float* Ap = X + (size_t)(rowBase + ar) * D_ + ac;
    // B slab 32x128 fp32
    const int br = tid >> 3;
    const int bc = (tid & 7) * 16;
    const float* Bp = W + (size_t)br * V_ + bc;

    for (int k0 = 0; k0 < D_; k0 += BK) {
        float4 a0 = *(const float4*)(Ap + k0);
        float4 a1 = *(const float4*)(Ap + k0 + 4);
        float4 a2 = *(const float4*)(Ap + k0 + 8);
        float4 a3 = *(const float4*)(Ap + k0 + 12);
        float4 b0 = *(const float4*)(Bp + (size_t)k0 * V_);
        float4 b1 = *(const float4*)(Bp + (size_t)k0 * V_ + 4);
        float4 b2 = *(const float4*)(Bp + (size_t)k0 * V_ + 8);
        float4 b3 = *(const float4*)(Bp + (size_t)k0 * V_ + 12);
        st4bf16(&As[ar][ac + 0], a0);  st4bf16(&As[ar][ac + 4], a1);
        st4bf16(&As[ar][ac + 8], a2);  st4bf16(&As[ar][ac + 12], a3);
        st4bf16(&Bs[br][bc + 0], b0);  st4bf16(&Bs[br][bc + 4], b1);
        st4bf16(&Bs[br][bc + 8], b2);  st4bf16(&Bs[br][bc + 12], b3);
        __syncthreads();

#pragma unroll
        for (int kk = 0; kk < BK; kk += 16) {
            wmma::fragment<wmma::matrix_a, 16, 16, 16, __nv_bfloat16, wmma::row_major> af[2];
            wmma::fragment<wmma::matrix_b, 16, 16, 16, __nv_bfloat16, wmma::row_major> bf[4];
#pragma unroll
            for (int i = 0; i < 2; ++i)
                wmma::load_matrix_sync(af[i], &As[warp_m * 32 + i * 16][kk], BK + APAD);
#pragma unroll
            for (int j = 0; j < 4; ++j)
                wmma::load_matrix_sync(bf[j], &Bs[kk][warp_n * 64 + j * 16], BN + BPAD);
#pragma unroll
            for (int i = 0; i < 2; ++i)
#pragma unroll
                for (int j = 0; j < 4; ++j)
                    wmma::mma_sync(cfrag[i][j], af[i], bf[j], cfrag[i][j]);
        }
        __syncthreads();
    }

    // Epilogue: 4 passes of 32 rows. Softmax per row, write log2(p + eps).
    const int tx = tid & 15;          // 8 cols each
    const int ty = tid >> 4;          // 16 groups, 2 rows each
    float bb[8];
#pragma unroll
    for (int j = 0; j < 8; ++j) bb[j] = bias[tx * 8 + j];

    for (int wm = 0; wm < 4; ++wm) {
        if (warp_m == wm) {
#pragma unroll
            for (int i = 0; i < 2; ++i)
#pragma unroll
                for (int j = 0; j < 4; ++j)
                    wmma::store_matrix_sync(&Cs[i * 16][warp_n * 64 + j * 16],
                                            cfrag[i][j], BN + CPAD, wmma::mem_row_major);
        }
        __syncthreads();
#pragma unroll
        for (int r = 0; r < 2; ++r) {
            const int row = ty * 2 + r;
            float l[8];
            float rmax = -CUDART_INF_F;
#pragma unroll
            for (int j = 0; j < 8; ++j) {
                l[j] = Cs[row][tx * 8 + j] + bb[j];
                rmax = fmaxf(rmax, l[j]);
            }
#pragma unroll
            for (int m = 1; m <= 8; m <<= 1)
                rmax = fmaxf(rmax, __shfl_xor_sync(0xFFFFFFFFu, rmax, m));
            float s = 0.f;
#pragma unroll
            for (int j = 0; j < 8; ++j) { l[j] = __expf(l[j] - rmax); s += l[j]; }
#pragma unroll
            for (int m = 1; m <= 8; m <<= 1)
                s += __shfl_xor_sync(0xFFFFFFFFu, s, m);
            float invs = 1.f / s;
            float* orow = g_lp + (size_t)(rowBase + wm * 32 + row) * V_ + tx * 8;
            float4 o0, o1;
            o0.x = __log2f(l[0] * invs + EPS_); o0.y = __log2f(l[1] * invs + EPS_);
            o0.z = __log2f(l[2] * invs + EPS_); o0.w = __log2f(l[3] * invs + EPS_);
            o1.x = __log2f(l[4] * invs + EPS_); o1.y = __log2f(l[5] * invs + EPS_);
            o1.z = __log2f(l[6] * invs + EPS_); o1.w = __log2f(l[7] * invs + EPS_);
            *(float4*)orow = o0;
            *(float4*)(orow + 4) = o1;
        }
        __syncthreads();
    }
}

// ---------------------------------------------------------------------------
// Kernel 2: CTC forward DP, log2 domain. One block per example, 288 threads,
// thread s owns state s (<257). g_lp already holds log2(p+eps), so per step
// the row is just staged smem<-register. 8-deep register FIFO hides the DRAM
// latency of the row loads (~800cyc / 8 ≈ 100 cyc amortized per step).
// ---------------------------------------------------------------------------
__global__ __launch_bounds__(288) void ctc_kernel(
    const int* __restrict__ targets, const int* __restrict__ tlen)
{
    __shared__ float alpha[2][S_];
    __shared__ float lps[2][V_];
    __shared__ int   exts[S_];

    const int b = blockIdx.x;
    const int tid = threadIdx.x;
    const float* LP = g_lp + (size_t)b * T_ * V_;

    if (tid < S_) exts[tid] = (tid & 1) ? targets[b * L_ + (tid >> 1)] : BLANK_;

    // Fill 8-deep prefetch FIFO with rows 0..7, stage row 0, load row 8.
    float pf[8];
    if (tid < V_) {
#pragma unroll
        for (int i = 0; i < 8; ++i) pf[i] = LP[(size_t)i * V_ + tid];
        lps[0][tid] = pf[0];
#pragma unroll
        for (int i = 0; i < 7; ++i) pf[i] = pf[i + 1];
        pf[7] = LP[(size_t)8 * V_ + tid];
    }
    __syncthreads();

    int  myext  = 0;
    bool allow2 = false;
    if (tid < S_) {
        myext  = exts[tid];
        allow2 = (tid & 1) && (tid >= 2) && (myext != exts[tid - 2]);
        alpha[0][tid] = (tid < 2) ? lps[0][myext] : NEG_;
    }

    for (int t = 1; t < T_; ++t) {
        const int cur = t & 1, prev = cur ^ 1;
        if (tid < V_) {
            lps[cur][tid] = pf[0];
#pragma unroll
            for (int i = 0; i < 7; ++i) pf[i] = pf[i + 1];
            if (t + 8 < T_) pf[7] = LP[(size_t)(t + 8) * V_ + tid];
        }
        __syncthreads();   // orders alpha[prev] writes (last iter) + lps[cur]

        if (tid < S_) {
            float a  = alpha[prev][tid];
            float a1 = (tid >= 1) ? alpha[prev][tid - 1] : NEG_;
            float a2 = allow2 ? alpha[prev][tid - 2] : NEG_;
            float m  = fmaxf(fmaxf(a, a1), a2);
            float s  = fexp2(a - m) + fexp2(a1 - m) + fexp2(a2 - m);
            alpha[cur][tid] = m + __log2f(s) + lps[cur][myext];
        }
    }
    __syncthreads();

    if (tid == 0) {
        const int last = 2 * tlen[b];              // 2..256
        // (T_-1)&1 == 1 -> final alpha lives in buffer 1.
        float aN  = alpha[1][last];
        float aN1 = alpha[1][last - 1];
        float m   = fmaxf(aN, aN1);
        g_loss[b] = -LN2_ * (m + __log2f(fexp2(aN - m) + fexp2(aN1 - m)));
    }
}

// ---------------------------------------------------------------------------
// Kernel 3: deterministic fixed-order sum of the 128 losses.
// ---------------------------------------------------------------------------
__global__ __launch_bounds__(128) void sum_kernel(float* __restrict__ out)
{
    __shared__ float s[128];
    const int t = threadIdx.x;
    s[t] = g_loss[t];
    __syncthreads();
    for (int o = 64; o > 0; o >>= 1) {
        if (t < o) s[t] += s[t + o];
        __syncthreads();
    }
    if (t == 0) out[0] = s[0];
}

extern "C" void kernel_launch(void* const* d_in, const int* in_sizes, int n_in,
                              void* d_out, int out_size)
{
    (void)in_sizes; (void)n_in; (void)out_size;
    const float* x       = (const float*)d_in[0];
    const float* W       = (const float*)d_in[1];
    const float* bias    = (const float*)d_in[2];
    const int*   targets = (const int*)d_in[3];
    const int*   tlength = (const int*)d_in[4];

    gemm_softmax_kernel<<<(B_ * T_) / BM, 256>>>(x, W, bias);
    ctc_kernel<<<B_, 288>>>(targets, tlength);
    sum_kernel<<<1, 128>>>((float*)d_out);
}

// round 7
// speedup vs baseline: 2.5356x; 1.8724x over previous
#include <cuda_runtime.h>
#include <cuda_bf16.h>
#include <math_constants.h>
#include <mma.h>

using namespace nvcuda;

// Problem constants
#define B_    128
#define T_    1024
#define D_    512
#define V_    128
#define L_    128
#define S_    257           // 2L+1
#define BLANK_ 127          // V-1
#define EPS_  1e-7f
#define NEG_  (-1e30f)
#define LN2_  0.6931471805599453f

// GEMM tiling
#define BM 128
#define BN 128
#define BK 32
#define APAD 8
#define BPAD 8
#define CPAD 4

// Scratch: log2(softmax prob + eps) [B,T,V] fp32 (64 MB), per-example losses
static __device__ float g_lp[B_ * T_ * V_];
static __device__ float g_loss[B_];

__device__ __forceinline__ float fexp2(float x) {
    float y; asm("ex2.approx.ftz.f32 %0, %1;" : "=f"(y) : "f"(x)); return y;
}

__device__ __forceinline__ void st4bf16(__nv_bfloat16* dst, float4 v) {
    __nv_bfloat162 p0; p0.x = __float2bfloat16(v.x); p0.y = __float2bfloat16(v.y);
    __nv_bfloat162 p1; p1.x = __float2bfloat16(v.z); p1.y = __float2bfloat16(v.w);
    *(__nv_bfloat162*)(dst)     = p0;
    *(__nv_bfloat162*)(dst + 2) = p1;
}

// ---------------------------------------------------------------------------
// Kernel 1: bf16 WMMA GEMM (logits = X @ W + b) + softmax -> g_lp = log2(p+eps)
// M = B*T = 131072, N = V = 128, K = D = 512. fp32 accumulate.
// Block 128x128, BK=32, 8 warps: warp grid 4(M) x 2(N), warp tile 32x64.
// Epilogue: 4 passes of 32 rows through smem; softmax via half-warp shuffles.
// ---------------------------------------------------------------------------
__global__ __launch_bounds__(256) void gemm_softmax_kernel(
    const float* __restrict__ X, const float* __restrict__ W,
    const float* __restrict__ bias)
{
    __shared__ __nv_bfloat16 As[BM][BK + APAD];   // 128 x 40
    __shared__ __nv_bfloat16 Bs[BK][BN + BPAD];   //  32 x 136
    __shared__ float         Cs[32][BN + CPAD];   //  32 x 132

    const int tid = threadIdx.x;
    const int wid = tid >> 5;
    const int warp_m = wid & 3;       // 0..3
    const int warp_n = wid >> 2;      // 0..1
    const int rowBase = blockIdx.x * BM;

    wmma::fragment<wmma::accumulator, 16, 16, 16, float> cfrag[2][4];
#pragma unroll
    for (int i = 0; i < 2; ++i)
#pragma unroll
        for (int j = 0; j < 4; ++j) wmma::fill_fragment(cfrag[i][j], 0.f);

    const int ar = tid >> 1;
    const int ac = (tid & 1) * 16;
    const float* Ap = X + (size_t)(rowBase + ar) * D_ + ac;
    const int br = tid >> 3;
    const int bc = (tid & 7) * 16;
    const float* Bp = W + (size_t)br * V_ + bc;

    for (int k0 = 0; k0 < D_; k0 += BK) {
        float4 a0 = *(const float4*)(Ap + k0);
        float4 a1 = *(const float4*)(Ap + k0 + 4);
        float4 a2 = *(const float4*)(Ap + k0 + 8);
        float4 a3 = *(const float4*)(Ap + k0 + 12);
        float4 b0 = *(const float4*)(Bp + (size_t)k0 * V_);
        float4 b1 = *(const float4*)(Bp + (size_t)k0 * V_ + 4);
        float4 b2 = *(const float4*)(Bp + (size_t)k0 * V_ + 8);
        float4 b3 = *(const float4*)(Bp + (size_t)k0 * V_ + 12);
        st4bf16(&As[ar][ac + 0], a0);  st4bf16(&As[ar][ac + 4], a1);
        st4bf16(&As[ar][ac + 8], a2);  st4bf16(&As[ar][ac + 12], a3);
        st4bf16(&Bs[br][bc + 0], b0);  st4bf16(&Bs[br][bc + 4], b1);
        st4bf16(&Bs[br][bc + 8], b2);  st4bf16(&Bs[br][bc + 12], b3);
        __syncthreads();

#pragma unroll
        for (int kk = 0; kk < BK; kk += 16) {
            wmma::fragment<wmma::matrix_a, 16, 16, 16, __nv_bfloat16, wmma::row_major> af[2];
            wmma::fragment<wmma::matrix_b, 16, 16, 16, __nv_bfloat16, wmma::row_major> bf[4];
#pragma unroll
            for (int i = 0; i < 2; ++i)
                wmma::load_matrix_sync(af[i], &As[warp_m * 32 + i * 16][kk], BK + APAD);
#pragma unroll
            for (int j = 0; j < 4; ++j)
                wmma::load_matrix_sync(bf[j], &Bs[kk][warp_n * 64 + j * 16], BN + BPAD);
#pragma unroll
            for (int i = 0; i < 2; ++i)
#pragma unroll
                for (int j = 0; j < 4; ++j)
                    wmma::mma_sync(cfrag[i][j], af[i], bf[j], cfrag[i][j]);
        }
        __syncthreads();
    }

    // Epilogue: 4 passes of 32 rows. Softmax per row, write log2(p + eps).
    const int tx = tid & 15;
    const int ty = tid >> 4;
    float bb[8];
#pragma unroll
    for (int j = 0; j < 8; ++j) bb[j] = bias[tx * 8 + j];

    for (int wm = 0; wm < 4; ++wm) {
        if (warp_m == wm) {
#pragma unroll
            for (int i = 0; i < 2; ++i)
#pragma unroll
                for (int j = 0; j < 4; ++j)
                    wmma::store_matrix_sync(&Cs[i * 16][warp_n * 64 + j * 16],
                                            cfrag[i][j], BN + CPAD, wmma::mem_row_major);
        }
        __syncthreads();
#pragma unroll
        for (int r = 0; r < 2; ++r) {
            const int row = ty * 2 + r;
            float l[8];
            float rmax = -CUDART_INF_F;
#pragma unroll
            for (int j = 0; j < 8; ++j) {
                l[j] = Cs[row][tx * 8 + j] + bb[j];
                rmax = fmaxf(rmax, l[j]);
            }
#pragma unroll
            for (int m = 1; m <= 8; m <<= 1)
                rmax = fmaxf(rmax, __shfl_xor_sync(0xFFFFFFFFu, rmax, m));
            float s = 0.f;
#pragma unroll
            for (int j = 0; j < 8; ++j) { l[j] = __expf(l[j] - rmax); s += l[j]; }
#pragma unroll
            for (int m = 1; m <= 8; m <<= 1)
                s += __shfl_xor_sync(0xFFFFFFFFu, s, m);
            float invs = 1.f / s;
            float* orow = g_lp + (size_t)(rowBase + wm * 32 + row) * V_ + tx * 8;
            float4 o0, o1;
            o0.x = __log2f(l[0] * invs + EPS_); o0.y = __log2f(l[1] * invs + EPS_);
            o0.z = __log2f(l[2] * invs + EPS_); o0.w = __log2f(l[3] * invs + EPS_);
            o1.x = __log2f(l[4] * invs + EPS_); o1.y = __log2f(l[5] * invs + EPS_);
            o1.z = __log2f(l[6] * invs + EPS_); o1.w = __log2f(l[7] * invs + EPS_);
            *(float4*)orow = o0;
            *(float4*)(orow + 4) = o1;
        }
        __syncthreads();
    }
}

// ---------------------------------------------------------------------------
// Kernel 2: CTC forward DP, log2 domain. One block per example, 288 threads,
// thread s owns state s (<257). Each state thread loads its OWN emission
// lp[t][myext] from global (one 512B row per step -> <=2 L2 req/warp) into a
// STATICALLY-indexed 8-deep FIFO: the t-loop is unrolled by 8 so e[j] is
// consumed exactly 8 barrier-steps after its load (true latency hiding —
// the previous register-rotating FIFO had effective depth 1).
// ---------------------------------------------------------------------------
__global__ __launch_bounds__(288) void ctc_kernel(
    const int* __restrict__ targets, const int* __restrict__ tlen)
{
    __shared__ float alpha[2][S_];
    __shared__ int   exts[S_];

    const int b = blockIdx.x;
    const int tid = threadIdx.x;
    const bool act = (tid < S_);
    const float* LP = g_lp + (size_t)b * T_ * V_;

    if (act) exts[tid] = (tid & 1) ? targets[b * L_ + (tid >> 1)] : BLANK_;
    __syncthreads();

    int  myext  = BLANK_;
    bool allow2 = false;
    if (act) {
        myext  = exts[tid];
        allow2 = (tid & 1) && (tid >= 2) && (myext != exts[tid - 2]);
    }

    // t = 0 init + prefetch FIFO for t = 1..8 (all 288 threads load; idle
    // lanes use BLANK_, coalesced within the same 512B row).
    if (act) alpha[0][tid] = (tid < 2) ? LP[myext] : NEG_;
    float e[8];
#pragma unroll
    for (int j = 0; j < 8; ++j) e[j] = LP[(size_t)(1 + j) * V_ + myext];
    __syncthreads();

    // Main chunks: t0 = 1, 9, ..., 1009 (127 chunks, steps t = 1..1016).
    for (int t0 = 1; t0 <= T_ - 15; t0 += 8) {
#pragma unroll
        for (int j = 0; j < 8; ++j) {
            const int cur  = (1 + j) & 1;     // t0 odd -> parity is (1+j)&1
            const int prev = cur ^ 1;
            if (act) {
                float a  = alpha[prev][tid];
                float a1 = (tid >= 1) ? alpha[prev][tid - 1] : NEG_;
                float a2 = allow2 ? alpha[prev][tid - 2] : NEG_;
                float m  = fmaxf(fmaxf(a, a1), a2);
                float s  = fexp2(a - m) + fexp2(a1 - m) + fexp2(a2 - m);
                alpha[cur][tid] = m + __log2f(s) + e[j];
            }
            const int tn = t0 + 8 + j;        // prefetch for step t0+8+j
            if (tn < T_) e[j] = LP[(size_t)tn * V_ + myext];
            __syncthreads();                  // orders alpha writes for next step
        }
    }
    // Tail: t = 1017..1023 (7 steps), emissions already in e[0..6].
#pragma unroll
    for (int j = 0; j < 7; ++j) {
        const int cur  = (1017 + j) & 1;
        const int prev = cur ^ 1;
        if (act) {
            float a  = alpha[prev][tid];
            float a1 = (tid >= 1) ? alpha[prev][tid - 1] : NEG_;
            float a2 = allow2 ? alpha[prev][tid - 2] : NEG_;
            float m  = fmaxf(fmaxf(a, a1), a2);
            float s  = fexp2(a - m) + fexp2(a1 - m) + fexp2(a2 - m);
            alpha[cur][tid] = m + __log2f(s) + e[j];
        }
        __syncthreads();
    }

    if (tid == 0) {
        const int last = 2 * tlen[b];              // 2..256
        // t = 1023 is odd -> final alpha lives in buffer 1.
        float aN  = alpha[1][last];
        float aN1 = alpha[1][last - 1];
        float m   = fmaxf(aN, aN1);
        g_loss[b] = -LN2_ * (m + __log2f(fexp2(aN - m) + fexp2(aN1 - m)));
    }
}

// ---------------------------------------------------------------------------
// Kernel 3: deterministic fixed-order sum of the 128 losses.
// ---------------------------------------------------------------------------
__global__ __launch_bounds__(128) void sum_kernel(float* __restrict__ out)
{
    __shared__ float s[128];
    const int t = threadIdx.x;
    s[t] = g_loss[t];
    __syncthreads();
    for (int o = 64; o > 0; o >>= 1) {
        if (t < o) s[t] += s[t + o];
        __syncthreads();
    }
    if (t == 0) out[0] = s[0];
}

extern "C" void kernel_launch(void* const* d_in, const int* in_sizes, int n_in,
                              void* d_out, int out_size)
{
    (void)in_sizes; (void)n_in; (void)out_size;
    const float* x       = (const float*)d_in[0];
    const float* W       = (const float*)d_in[1];
    const float* bias    = (const float*)d_in[2];
    const int*   targets = (const int*)d_in[3];
    const int*   tlength = (const int*)d_in[4];

    gemm_softmax_kernel<<<(B_ * T_) / BM, 256>>>(x, W, bias);
    ctc_kernel<<<B_, 288>>>(targets, tlength);
    sum_kernel<<<1, 128>>>((float*)d_out);
}